// round 2
// baseline (speedup 1.0000x reference)
#include <cuda_runtime.h>
#include <cuda_bf16.h>
#include <mma.h>

using namespace nvcuda;

#define NN  512
#define BSZ 64
#define TT  200
#define DD  32

static constexpr size_t MAT = (size_t)BSZ * NN * NN;   // 16,777,216 elements

// Scratch (device globals: allocation-free rule)
__device__ __nv_bfloat16 g_P[MAT];   // A1/n in bf16
__device__ __nv_bfloat16 g_Q[MAT];   // P^2
__device__ __nv_bfloat16 g_M[MAT];   // P + P^2 + P^3

// ---------------------------------------------------------------------------
// Convert: P = bf16(adj * (1/512))
// ---------------------------------------------------------------------------
__global__ void k_convert(const float* __restrict__ adj, __nv_bfloat16* __restrict__ P) {
    size_t i = ((size_t)blockIdx.x * blockDim.x + threadIdx.x) * 4;
    float4 v = *(const float4*)(adj + i);
    const float s = 1.0f / 512.0f;
    __nv_bfloat162 p0 = __floats2bfloat162_rn(v.x * s, v.y * s);
    __nv_bfloat162 p1 = __floats2bfloat162_rn(v.z * s, v.w * s);
    uint2 u;
    u.x = *(unsigned*)&p0;
    u.y = *(unsigned*)&p1;
    *(uint2*)(P + i) = u;
}

// ---------------------------------------------------------------------------
// M = bf16(M + P + Q)   (M holds Q@P after second GEMM)
// ---------------------------------------------------------------------------
__device__ __forceinline__ float2 bf2_to_f2(unsigned u) {
    __nv_bfloat162 h = *(__nv_bfloat162*)&u;
    return make_float2(__low2float(h), __high2float(h));
}

__global__ void k_add(__nv_bfloat16* __restrict__ M,
                      const __nv_bfloat16* __restrict__ P,
                      const __nv_bfloat16* __restrict__ Q) {
    size_t i = ((size_t)blockIdx.x * blockDim.x + threadIdx.x) * 4;
    uint2 um = *(uint2*)(M + i);
    uint2 up = *(const uint2*)(P + i);
    uint2 uq = *(const uint2*)(Q + i);
    float2 m0 = bf2_to_f2(um.x), m1 = bf2_to_f2(um.y);
    float2 p0 = bf2_to_f2(up.x), p1 = bf2_to_f2(up.y);
    float2 q0 = bf2_to_f2(uq.x), q1 = bf2_to_f2(uq.y);
    __nv_bfloat162 r0 = __floats2bfloat162_rn(m0.x + p0.x + q0.x, m0.y + p0.y + q0.y);
    __nv_bfloat162 r1 = __floats2bfloat162_rn(m1.x + p1.x + q1.x, m1.y + p1.y + q1.y);
    uint2 u;
    u.x = *(unsigned*)&r0;
    u.y = *(unsigned*)&r1;
    *(uint2*)(M + i) = u;
}

// ---------------------------------------------------------------------------
// Batched bf16 GEMM: C[b] = A[b] @ B[b], 512x512x512, fp32 accum, bf16 out.
// Block tile 128x128, BK=64, 8 warps (each 32x64), cp.async double buffer.
// ---------------------------------------------------------------------------
__device__ __forceinline__ void cp16(void* s, const void* g) {
    unsigned sa = (unsigned)__cvta_generic_to_shared(s);
    asm volatile("cp.async.cg.shared.global [%0], [%1], 16;\n" :: "r"(sa), "l"(g));
}

__global__ void __launch_bounds__(256) k_gemm(const __nv_bfloat16* __restrict__ A,
                                              const __nv_bfloat16* __restrict__ B,
                                              __nv_bfloat16* __restrict__ C) {
    extern __shared__ __nv_bfloat16 smg[];
    __nv_bfloat16* As = smg;                 // [2][128*64]
    __nv_bfloat16* Bs = smg + 2 * 128 * 64;  // [2][64*128]

    const int tid = threadIdx.x;
    const int b   = blockIdx.z;
    const int bm0 = blockIdx.y * 128;
    const int bn0 = blockIdx.x * 128;
    const __nv_bfloat16* Ab = A + (size_t)b * NN * NN;
    const __nv_bfloat16* Bb = B + (size_t)b * NN * NN;

    const int ar = tid >> 3, ac = (tid & 7) * 8;     // A tile: 128 rows x 64 cols
    const int br = tid >> 4, bc = (tid & 15) * 8;    // B tile:  64 rows x 128 cols

    auto load_tiles = [&](int st, int k0) {
        __nv_bfloat16* a  = As + st * 8192;
        __nv_bfloat16* bt = Bs + st * 8192;
#pragma unroll
        for (int rr = 0; rr < 128; rr += 32)
            cp16(a + (ar + rr) * 64 + ac, Ab + (size_t)(bm0 + ar + rr) * NN + k0 + ac);
#pragma unroll
        for (int rr = 0; rr < 64; rr += 16)
            cp16(bt + (br + rr) * 128 + bc, Bb + (size_t)(k0 + br + rr) * NN + bn0 + bc);
        asm volatile("cp.async.commit_group;\n");
    };

    const int w  = tid >> 5;
    const int wm = w >> 1;   // 0..3
    const int wn = w & 1;    // 0..1

    wmma::fragment<wmma::accumulator, 16, 16, 16, float> cf[2][4];
#pragma unroll
    for (int i = 0; i < 2; i++)
#pragma unroll
        for (int j = 0; j < 4; j++) wmma::fill_fragment(cf[i][j], 0.0f);

    load_tiles(0, 0);
#pragma unroll
    for (int kt = 0; kt < 8; ++kt) {
        asm volatile("cp.async.wait_group 0;\n");
        __syncthreads();
        if (kt < 7) load_tiles((kt + 1) & 1, (kt + 1) * 64);
        const __nv_bfloat16* a  = As + (kt & 1) * 8192;
        const __nv_bfloat16* bt = Bs + (kt & 1) * 8192;
#pragma unroll
        for (int kk = 0; kk < 4; ++kk) {
            wmma::fragment<wmma::matrix_a, 16, 16, 16, __nv_bfloat16, wmma::row_major> af[2];
            wmma::fragment<wmma::matrix_b, 16, 16, 16, __nv_bfloat16, wmma::row_major> bfr[4];
#pragma unroll
            for (int i = 0; i < 2; i++)
                wmma::load_matrix_sync(af[i], a + (wm * 32 + i * 16) * 64 + kk * 16, 64);
#pragma unroll
            for (int j = 0; j < 4; j++)
                wmma::load_matrix_sync(bfr[j], bt + (kk * 16) * 128 + wn * 64 + j * 16, 128);
#pragma unroll
            for (int i = 0; i < 2; i++)
#pragma unroll
                for (int j = 0; j < 4; j++)
                    wmma::mma_sync(cf[i][j], af[i], bfr[j], cf[i][j]);
        }
        __syncthreads();
    }

    // Epilogue: spill accumulators to smem (reuse 64KB), convert to bf16
    float* Cs = (float*)smg;
#pragma unroll
    for (int i = 0; i < 2; i++)
#pragma unroll
        for (int j = 0; j < 4; j++)
            wmma::store_matrix_sync(Cs + (wm * 32 + i * 16) * 128 + wn * 64 + j * 16,
                                    cf[i][j], 128, wmma::mem_row_major);
    __syncthreads();

    int rl = tid >> 1, half = tid & 1;
    __nv_bfloat16* Cg = C + (size_t)b * NN * NN + (size_t)(bm0 + rl) * NN + bn0 + half * 64;
    const float* src = Cs + rl * 128 + half * 64;
#pragma unroll
    for (int c = 0; c < 64; c += 4) {
        float4 v = *(const float4*)(src + c);
        __nv_bfloat162 p0 = __floats2bfloat162_rn(v.x, v.y);
        __nv_bfloat162 p1 = __floats2bfloat162_rn(v.z, v.w);
        uint2 u;
        u.x = *(unsigned*)&p0;
        u.y = *(unsigned*)&p1;
        *(uint2*)(Cg + c) = u;
    }
}

// ---------------------------------------------------------------------------
// Persistent scan: one CTA per batch, 512 threads, 199 sequential steps.
// All weights + node embeddings + state live in shared memory.
// ---------------------------------------------------------------------------
// smem layout (float offsets)
#define OFF_NREC  0        // [32][512]
#define OFF_NSEND 16384    // [32][512]
#define OFF_LP    32768    // [2][512]
#define OFF_NLF   33792    // [2][512]
#define OFF_LP2   34816    // [512] unsigned (bf16x2 dup of lp)
#define OFF_PART  35328    // [4][512]
#define OFF_UB    37376    // [2][32]
#define OFF_UF    37440    // [2][32]
#define OFF_H     37504    // [32]
#define OFF_UU    37536    // [32]
#define OFF_W1    37568    // [160][32]
#define OFF_W2    42688    // [32][32]
#define OFF_WF    43712    // [32][32]
#define OFF_WB    44736    // [32][32]
#define OFF_B1    45760
#define OFF_B2    45792
#define OFF_BFB   45824
#define OFF_BBB   45856
#define SCAN_SMEM_FLOATS 45888
#define SCAN_SMEM_BYTES  (SCAN_SMEM_FLOATS * 4)

__global__ void __launch_bounds__(512, 1) k_scan(
    const int* __restrict__ skills, const int* __restrict__ times_,
    const float* __restrict__ labels, const float* __restrict__ nemb,
    const float* __restrict__ ub0, const float* __restrict__ uf0,
    const float* __restrict__ cw1, const float* __restrict__ cb1,
    const float* __restrict__ cw2, const float* __restrict__ cb2,
    const float* __restrict__ lfw, const float* __restrict__ lfb,
    const float* __restrict__ lbw, const float* __restrict__ lbb,
    const __nv_bfloat16* __restrict__ Mg, float* __restrict__ out) {

    extern __shared__ float smf[];
    float*    nrec  = smf + OFF_NREC;
    float*    nsend = smf + OFF_NSEND;
    float*    lp    = smf + OFF_LP;
    float*    nlf   = smf + OFF_NLF;
    unsigned* lp2   = (unsigned*)(smf + OFF_LP2);
    float*    part  = smf + OFF_PART;
    float*    ub    = smf + OFF_UB;
    float*    uf    = smf + OFF_UF;
    float*    hbuf  = smf + OFF_H;
    float*    uubuf = smf + OFF_UU;
    float*    w1t   = smf + OFF_W1;
    float*    w2t   = smf + OFF_W2;
    float*    wft   = smf + OFF_WF;
    float*    wbt   = smf + OFF_WB;
    float*    b1s   = smf + OFF_B1;
    float*    b2s   = smf + OFF_B2;
    float*    bfs   = smf + OFF_BFB;
    float*    bbs   = smf + OFF_BBB;

    const int b   = blockIdx.x;
    const int tid = threadIdx.x;

    // ---- one-time init ----
    for (int i = tid; i < NN * DD; i += 512) {
        int k = i >> 5, d = i & 31;
        nsend[d * NN + k] = nemb[k * 64 + d];        // node_send = emb[:, :D]
        nrec[d * NN + k]  = nemb[k * 64 + 32 + d];   // node_rec  = emb[:, D:]
    }
    for (int i = tid; i < 5120; i += 512) {          // conv1_w (o,c,l) -> [c*5+l][o]
        int o = i / 160, r = i % 160;
        w1t[r * 32 + o] = cw1[i];
    }
    for (int i = tid; i < 1024; i += 512) {
        int o = i >> 5, r = i & 31;
        w2t[r * 32 + o] = cw2[i];
        wft[r * 32 + o] = lfw[i];
        wbt[r * 32 + o] = lbw[i];
    }
    if (tid < 32) {
        b1s[tid] = cb1[tid];  b2s[tid] = cb2[tid];
        bfs[tid] = lfb[tid];  bbs[tid] = lbb[tid];
        ub[tid]  = ub0[b * 32 + tid];
        uf[tid]  = uf0[b * 32 + tid];
    }
    __syncthreads();

    // carry init: last_perf0 = ub0 @ nrec^T, nlf0 = uf0 @ nsend^T
    {
        float l0 = 0.f, f0 = 0.f;
#pragma unroll
        for (int d = 0; d < 32; d++) {
            l0 += ub[d] * nrec[d * NN + tid];
            f0 += uf[d] * nsend[d * NN + tid];
        }
        lp[tid]  = l0;
        nlf[tid] = f0;
        __nv_bfloat162 dd = __float2bfloat162_rn(l0);
        lp2[tid] = *(unsigned*)&dd;
    }
    __syncthreads();

    const int jg = tid >> 7;        // 0..3 : j-chunk of 128
    const int kg = tid & 127;       // 0..127: 4 consecutive k columns
    const uint2* mbase = (const uint2*)(Mg + ((size_t)b << 18)) + jg * (128 * 128) + kg;

    const float inv1536 = 1.0f / 1536.0f;
    const float invlog5 = 0.6213349345596119f;   // 1/ln(5)

    for (int s = 0; s < TT - 1; ++s) {
        const int cp = s & 1, np = cp ^ 1;
        const int   skill = skills[b * TT + s + 1];
        const float lab   = labels[b * TT + s + 1];
        const float dtv   = fabsf((float)(times_[b * TT + s + 1] - times_[b * TT + s]));
        const float delta = logf(dtv + 1e-6f) * invlog5;

        // --- phase 1 (reads carry) ---
        float bse = 0.f, nn = 0.f;
#pragma unroll
        for (int d = 0; d < 32; d++) {
            bse += ub[cp * 32 + d] * nrec[d * NN + tid];
            nn  += uf[cp * 32 + d] * nsend[d * NN + tid];
        }
        const float tmp = expf(-delta * 0.1f * nlf[cp * NN + tid]) * lp[cp * NN + tid];

        // GEMV partials: this thread owns columns 4*kg..4*kg+3, j-range jg*128..+127
        __nv_bfloat162 a0 = __float2bfloat162_rn(0.f);
        __nv_bfloat162 a1 = a0;
        const unsigned* lps = lp2 + (jg << 7);
#pragma unroll 8
        for (int j = 0; j < 128; ++j) {
            uint2 mv = mbase[(size_t)j * 128];
            unsigned lv = lps[j];
            __nv_bfloat162 l2 = *(__nv_bfloat162*)&lv;
            a0 = __hfma2(l2, *(__nv_bfloat162*)&mv.x, a0);
            a1 = __hfma2(l2, *(__nv_bfloat162*)&mv.y, a1);
        }
        *(float4*)&part[jg * NN + (kg << 2)] =
            make_float4(__low2float(a0), __high2float(a0), __low2float(a1), __high2float(a1));

        __syncthreads();

        // --- phase 2 (writes next carry) ---
        const float spat = (part[tid] + part[NN + tid] + part[2 * NN + tid] + part[3 * NN + tid]) * inv1536;
        const float x    = bse + tmp + spat;
        const float cur  = 1.0f / (1.0f + expf(-x));
        lp[np * NN + tid]  = cur;
        nlf[np * NN + tid] = nn;
        __nv_bfloat162 cd = __float2bfloat162_rn(cur);
        lp2[tid] = *(unsigned*)&cd;
        if (tid == skill) out[s * BSZ + b] = cur;

        // tiny MLP on warp 0
        if (tid < 32) {
            const int o = tid;
            float hv = b1s[o];
#pragma unroll
            for (int c = 0; c < 32; ++c) {
                float u0 = ub[cp * 32 + c], u1 = uf[cp * 32 + c];
                float u3 = nrec[c * NN + skill], u4 = nsend[c * NN + skill];
                const float* w = w1t + c * 5 * 32 + o;
                hv += u0 * w[0] + u1 * w[32] + lab * w[64] + u3 * w[96] + u4 * w[128];
            }
            hbuf[o] = fmaxf(hv, 0.f);
            __syncwarp();
            float uu = b2s[o];
#pragma unroll
            for (int i2 = 0; i2 < 32; i2++) uu += hbuf[i2] * w2t[i2 * 32 + o];
            uubuf[o] = uu;
            __syncwarp();
            float af = bfs[o], ab = bbs[o];
#pragma unroll
            for (int i2 = 0; i2 < 32; i2++) {
                float u = uubuf[i2];
                af += u * wft[i2 * 32 + o];
                ab += u * wbt[i2 * 32 + o];
            }
            ub[np * 32 + o] = tanhf(ab);   // new user_b from lin_b
            uf[np * 32 + o] = tanhf(af);   // new user_f from lin_f
        }
        __syncthreads();
    }
}

// ---------------------------------------------------------------------------
extern "C" void kernel_launch(void* const* d_in, const int* in_sizes, int n_in,
                              void* d_out, int out_size) {
    const int*   skills = (const int*)  d_in[0];
    const int*   times_ = (const int*)  d_in[1];
    const float* labels = (const float*)d_in[2];
    const float* adj    = (const float*)d_in[3];
    const float* nemb   = (const float*)d_in[4];
    const float* ub0    = (const float*)d_in[5];
    const float* uf0    = (const float*)d_in[6];
    const float* cw1    = (const float*)d_in[7];
    const float* cb1    = (const float*)d_in[8];
    const float* cw2    = (const float*)d_in[9];
    const float* cb2    = (const float*)d_in[10];
    const float* lfw    = (const float*)d_in[11];
    const float* lfb    = (const float*)d_in[12];
    const float* lbw    = (const float*)d_in[13];
    const float* lbb    = (const float*)d_in[14];

    void *pP = nullptr, *pQ = nullptr, *pM = nullptr;
    cudaGetSymbolAddress(&pP, g_P);
    cudaGetSymbolAddress(&pQ, g_Q);
    cudaGetSymbolAddress(&pM, g_M);
    __nv_bfloat16* P = (__nv_bfloat16*)pP;
    __nv_bfloat16* Q = (__nv_bfloat16*)pQ;
    __nv_bfloat16* M = (__nv_bfloat16*)pM;

    cudaFuncSetAttribute(k_gemm, cudaFuncAttributeMaxDynamicSharedMemorySize, 65536);
    cudaFuncSetAttribute(k_scan, cudaFuncAttributeMaxDynamicSharedMemorySize, SCAN_SMEM_BYTES);

    // P = A1/n
    k_convert<<<16384, 256>>>(adj, P);
    // Q = P@P ; M(tmp) = Q@P ; M = P + Q + Q@P
    dim3 g(4, 4, 64);
    k_gemm<<<g, 256, 65536>>>(P, P, Q);
    k_gemm<<<g, 256, 65536>>>(Q, P, M);
    k_add<<<16384, 256>>>(M, P, Q);
    // persistent per-batch scan
    k_scan<<<BSZ, 512, SCAN_SMEM_BYTES>>>(skills, times_, labels, nemb, ub0, uf0,
                                          cw1, cb1, cw2, cb2, lfw, lfb, lbw, lbb,
                                          M, (float*)d_out);
}

// round 3
// speedup vs baseline: 1.3989x; 1.3989x over previous
#include <cuda_runtime.h>
#include <cuda_bf16.h>
#include <cuda_fp16.h>
#include <mma.h>
using namespace nvcuda;

#define NN  512
#define BSZ 64
#define TT  200

static constexpr size_t MAT = (size_t)BSZ * NN * NN;
__device__ __nv_bfloat16 g_P[MAT];
__device__ __nv_bfloat16 g_Q[MAT];
__device__ __nv_bfloat16 g_M[MAT];

__global__ void k_convert(const float* __restrict__ adj, __nv_bfloat16* __restrict__ P) {
    size_t i = ((size_t)blockIdx.x * blockDim.x + threadIdx.x) * 4;
    float4 v = *(const float4*)(adj + i);
    const float s = 1.0f / 512.0f;
    __nv_bfloat162 p0 = __floats2bfloat162_rn(v.x * s, v.y * s);
    __nv_bfloat162 p1 = __floats2bfloat162_rn(v.z * s, v.w * s);
    uint2 u; u.x = *(unsigned*)&p0; u.y = *(unsigned*)&p1;
    *(uint2*)(P + i) = u;
}

__device__ __forceinline__ float2 bf2f2(unsigned u) {
    __nv_bfloat162 h = *(__nv_bfloat162*)&u;
    return make_float2(__low2float(h), __high2float(h));
}

__global__ void k_add(__nv_bfloat16* __restrict__ M, const __nv_bfloat16* __restrict__ P,
                      const __nv_bfloat16* __restrict__ Q) {
    size_t i = ((size_t)blockIdx.x * blockDim.x + threadIdx.x) * 4;
    uint2 um = *(uint2*)(M + i), up = *(const uint2*)(P + i), uq = *(const uint2*)(Q + i);
    float2 m0 = bf2f2(um.x), m1 = bf2f2(um.y), p0 = bf2f2(up.x), p1 = bf2f2(up.y);
    float2 q0 = bf2f2(uq.x), q1 = bf2f2(uq.y);
    __nv_bfloat162 r0 = __floats2bfloat162_rn(m0.x + p0.x + q0.x, m0.y + p0.y + q0.y);
    __nv_bfloat162 r1 = __floats2bfloat162_rn(m1.x + p1.x + q1.x, m1.y + p1.y + q1.y);
    uint2 u; u.x = *(unsigned*)&r0; u.y = *(unsigned*)&r1;
    *(uint2*)(M + i) = u;
}

__device__ __forceinline__ void cp16(void* s, const void* g) {
    unsigned sa = (unsigned)__cvta_generic_to_shared(s);
    asm volatile("cp.async.cg.shared.global [%0], [%1], 16;\n" :: "r"(sa), "l"(g));
}

__global__ void __launch_bounds__(256) k_gemm(const __nv_bfloat16* __restrict__ A,
                                              const __nv_bfloat16* __restrict__ B,
                                              __nv_bfloat16* __restrict__ C) {
    extern __shared__ __nv_bfloat16 smg[];
    __nv_bfloat16* As = smg;
    __nv_bfloat16* Bs = smg + 2 * 128 * 64;
    const int tid = threadIdx.x, b = blockIdx.z;
    const int bm0 = blockIdx.y * 128, bn0 = blockIdx.x * 128;
    const __nv_bfloat16* Ab = A + (size_t)b * NN * NN;
    const __nv_bfloat16* Bb = B + (size_t)b * NN * NN;
    const int ar = tid >> 3, ac = (tid & 7) * 8;
    const int br = tid >> 4, bc = (tid & 15) * 8;
    auto load_tiles = [&](int st, int k0) {
        __nv_bfloat16* a = As + st * 8192;
        __nv_bfloat16* bt = Bs + st * 8192;
#pragma unroll
        for (int rr = 0; rr < 128; rr += 32)
            cp16(a + (ar + rr) * 64 + ac, Ab + (size_t)(bm0 + ar + rr) * NN + k0 + ac);
#pragma unroll
        for (int rr = 0; rr < 64; rr += 16)
            cp16(bt + (br + rr) * 128 + bc, Bb + (size_t)(k0 + br + rr) * NN + bn0 + bc);
        asm volatile("cp.async.commit_group;\n");
    };
    const int w = tid >> 5, wm = w >> 1, wn = w & 1;
    wmma::fragment<wmma::accumulator, 16, 16, 16, float> cf[2][4];
#pragma unroll
    for (int i = 0; i < 2; i++)
#pragma unroll
        for (int j = 0; j < 4; j++) wmma::fill_fragment(cf[i][j], 0.0f);
    load_tiles(0, 0);
#pragma unroll
    for (int kt = 0; kt < 8; ++kt) {
        asm volatile("cp.async.wait_group 0;\n");
        __syncthreads();
        if (kt < 7) load_tiles((kt + 1) & 1, (kt + 1) * 64);
        const __nv_bfloat16* a = As + (kt & 1) * 8192;
        const __nv_bfloat16* bt = Bs + (kt & 1) * 8192;
#pragma unroll
        for (int kk = 0; kk < 4; ++kk) {
            wmma::fragment<wmma::matrix_a, 16, 16, 16, __nv_bfloat16, wmma::row_major> af[2];
            wmma::fragment<wmma::matrix_b, 16, 16, 16, __nv_bfloat16, wmma::row_major> bfr[4];
#pragma unroll
            for (int i = 0; i < 2; i++)
                wmma::load_matrix_sync(af[i], a + (wm * 32 + i * 16) * 64 + kk * 16, 64);
#pragma unroll
            for (int j = 0; j < 4; j++)
                wmma::load_matrix_sync(bfr[j], bt + (kk * 16) * 128 + wn * 64 + j * 16, 128);
#pragma unroll
            for (int i = 0; i < 2; i++)
#pragma unroll
                for (int j = 0; j < 4; j++)
                    wmma::mma_sync(cf[i][j], af[i], bfr[j], cf[i][j]);
        }
        __syncthreads();
    }
    float* Cs = (float*)smg;
#pragma unroll
    for (int i = 0; i < 2; i++)
#pragma unroll
        for (int j = 0; j < 4; j++)
            wmma::store_matrix_sync(Cs + (wm * 32 + i * 16) * 128 + wn * 64 + j * 16,
                                    cf[i][j], 128, wmma::mem_row_major);
    __syncthreads();
    int rl = tid >> 1, half = tid & 1;
    __nv_bfloat16* Cg = C + (size_t)b * NN * NN + (size_t)(bm0 + rl) * NN + bn0 + half * 64;
    const float* src = Cs + rl * 128 + half * 64;
#pragma unroll
    for (int c = 0; c < 64; c += 4) {
        float4 v = *(const float4*)(src + c);
        __nv_bfloat162 p0 = __floats2bfloat162_rn(v.x, v.y);
        __nv_bfloat162 p1 = __floats2bfloat162_rn(v.z, v.w);
        uint2 u; u.x = *(unsigned*)&p0; u.y = *(unsigned*)&p1;
        *(uint2*)(Cg + c) = u;
    }
}

// ---------------------------------------------------------------------------
// Cluster scan: 2 CTAs per batch. fp8 M' (=256*M) j-split, SMEM-resident.
// ---------------------------------------------------------------------------
#define KGS   2056                   // bytes per k-group (256 j * 8 + 8 pad)
#define OFF_MQ    0                  // 64 * 2056 = 131584
#define OFF_PART  131584             // float[8][512]
#define OFF_PARTR 147968             // float[2][512]
#define OFF_LP2   152064             // u32[2][512]
#define OFF_W1    156160             // float[160][32]
#define OFF_W2    176640
#define OFF_WF    180736
#define OFF_WB    184832
#define OFF_BIAS  188928             // 4*32 floats
#define OFF_UB    189440             // float[2][32]
#define OFF_UF    189696
#define OFF_H     189952
#define OFF_UU    190080
#define OFF_SKC   190208             // float[64]
#define OFF_DEL   190464             // float[200]
#define OFF_LAB   191264
#define OFF_SKL   192064
#define OFF_BAR   192864             // 2 mbarriers
#define SCAN_SMEM 192880

__device__ __forceinline__ unsigned smem_u32(const void* p) {
    unsigned r;
    asm("{ .reg .u64 t; cvta.to.shared.u64 t, %1; cvt.u32.u64 %0, t; }" : "=r"(r) : "l"(p));
    return r;
}
__device__ __forceinline__ unsigned mapa_u32(unsigned a, unsigned rank) {
    unsigned r;
    asm("mapa.shared::cluster.u32 %0, %1, %2;" : "=r"(r) : "r"(a), "r"(rank));
    return r;
}
__device__ __forceinline__ void bar_wait_acq(unsigned a, unsigned parity) {
    unsigned done;
    asm volatile("{\n\t.reg .pred p;\n\t"
        "mbarrier.try_wait.parity.acquire.cluster.shared::cta.b64 p, [%1], %2;\n\t"
        "selp.b32 %0, 1, 0, p;\n\t}" : "=r"(done) : "r"(a), "r"(parity) : "memory");
    while (!done)
        asm volatile("{\n\t.reg .pred p;\n\t"
            "mbarrier.try_wait.parity.acquire.cluster.shared::cta.b64 p, [%1], %2, 0x989680;\n\t"
            "selp.b32 %0, 1, 0, p;\n\t}" : "=r"(done) : "r"(a), "r"(parity) : "memory");
}
__device__ __forceinline__ void fp8x8_to_h2(unsigned lo, unsigned hi,
                                            __half2& h0, __half2& h1, __half2& h2, __half2& h3) {
    unsigned r0, r1, r2, r3;
    asm("{\n\t.reg .b16 a,b,c,d;\n\t"
        "mov.b32 {a,b}, %4;\n\tmov.b32 {c,d}, %5;\n\t"
        "cvt.rn.f16x2.e4m3x2 %0, a;\n\tcvt.rn.f16x2.e4m3x2 %1, b;\n\t"
        "cvt.rn.f16x2.e4m3x2 %2, c;\n\tcvt.rn.f16x2.e4m3x2 %3, d;\n\t}"
        : "=r"(r0), "=r"(r1), "=r"(r2), "=r"(r3) : "r"(lo), "r"(hi));
    h0 = *(__half2*)&r0; h1 = *(__half2*)&r1; h2 = *(__half2*)&r2; h3 = *(__half2*)&r3;
}

__global__ void __launch_bounds__(512, 1) __cluster_dims__(2, 1, 1)
k_scan(const int* __restrict__ skills, const int* __restrict__ times_,
       const float* __restrict__ labels, const float* __restrict__ nemb,
       const float* __restrict__ ub0, const float* __restrict__ uf0,
       const float* __restrict__ cw1, const float* __restrict__ cb1,
       const float* __restrict__ cw2, const float* __restrict__ cb2,
       const float* __restrict__ lfw, const float* __restrict__ lfb,
       const float* __restrict__ lbw, const float* __restrict__ lbb,
       const __nv_bfloat16* __restrict__ Mg, float* __restrict__ out) {

    extern __shared__ char smb[];
    char*     mq    = smb + OFF_MQ;
    float*    parts = (float*)(smb + OFF_PART);
    float*    partR = (float*)(smb + OFF_PARTR);
    unsigned* lp2   = (unsigned*)(smb + OFF_LP2);
    float*    w1t   = (float*)(smb + OFF_W1);
    float*    w2t   = (float*)(smb + OFF_W2);
    float*    wft   = (float*)(smb + OFF_WF);
    float*    wbt   = (float*)(smb + OFF_WB);
    float*    bias  = (float*)(smb + OFF_BIAS);
    float*    ubuf  = (float*)(smb + OFF_UB);
    float*    ufbuf = (float*)(smb + OFF_UF);
    float*    hbuf  = (float*)(smb + OFF_H);
    float*    uubuf = (float*)(smb + OFF_UU);
    float*    skc   = (float*)(smb + OFF_SKC);
    float*    del_s = (float*)(smb + OFF_DEL);
    float*    lab_s = (float*)(smb + OFF_LAB);
    int*      skl_s = (int*)(smb + OFF_SKL);

    const int tid = threadIdx.x;
    const int b = blockIdx.x >> 1;
    unsigned rank;
    asm("mov.u32 %0, %%cluster_ctarank;" : "=r"(rank));
    const unsigned peer = rank ^ 1;

    const unsigned sbase  = smem_u32(smb);
    const unsigned bar_a  = sbase + OFF_BAR;
    const unsigned pr_a   = sbase + OFF_PARTR;
    const unsigned r_pr   = mapa_u32(pr_a, peer);
    const unsigned r_bar  = mapa_u32(bar_a, peer);

    if (tid == 0) {
        asm volatile("mbarrier.init.shared.b64 [%0], 512;" :: "r"(bar_a) : "memory");
        asm volatile("mbarrier.init.shared.b64 [%0], 512;" :: "r"(bar_a + 8) : "memory");
    }

    for (int i = tid; i < 5120; i += 512) { int o = i / 160, r = i % 160; w1t[r * 32 + o] = cw1[i]; }
    for (int i = tid; i < 1024; i += 512) {
        int o = i >> 5, r = i & 31;
        w2t[r * 32 + o] = cw2[i]; wft[r * 32 + o] = lfw[i]; wbt[r * 32 + o] = lbw[i];
    }
    if (tid < 32) {
        bias[tid] = cb1[tid]; bias[32 + tid] = cb2[tid];
        bias[64 + tid] = lfb[tid]; bias[96 + tid] = lbb[tid];
        ubuf[tid] = ub0[b * 32 + tid]; ufbuf[tid] = uf0[b * 32 + tid];
    }
    const float invlog5 = 0.6213349345596119f;
    for (int s = tid; s < TT - 1; s += 512) {
        float dtv = fabsf((float)(times_[b * TT + s + 1] - times_[b * TT + s]));
        del_s[s] = logf(dtv + 1e-6f) * invlog5;
        lab_s[s] = labels[b * TT + s + 1];
        skl_s[s] = skills[b * TT + s + 1];
    }

    // node-embedding columns for node `tid` in registers
    float nr[32], ns[32];
#pragma unroll
    for (int d = 0; d < 32; d++) {
        ns[d] = nemb[tid * 64 + d];
        nr[d] = nemb[tid * 64 + 32 + d];
    }

    // fp8 M' fill: rows j in [rank*256, rank*256+256), all 512 k
    {
        const __nv_bfloat16* Mb = Mg + ((size_t)b << 18) + (size_t)(rank * 256) * NN;
        for (int pi = tid; pi < 65536; pi += 512) {
            int j = pi >> 8, kp = pi & 255;        // kp: pair of cols
            int kk = kp * 2, kg = kk >> 3, ci = kk & 7;
            unsigned v = *(const unsigned*)(Mb + (size_t)j * NN + kk);
            __nv_bfloat162 h = *(__nv_bfloat162*)&v;
            float f0 = __low2float(h) * 256.0f, f1 = __high2float(h) * 256.0f;
            unsigned short r;
            asm("cvt.rn.satfinite.e4m3x2.f32 %0, %1, %2;" : "=h"(r) : "f"(f1), "f"(f0));
            *(unsigned short*)(mq + kg * KGS + j * 8 + ci) = r;
        }
    }
    __syncthreads();

    // initial carry
    float lp_reg = 0.f, nlf_reg = 0.f;
#pragma unroll
    for (int d = 0; d < 32; d++) {
        lp_reg  += ubuf[d] * nr[d];
        nlf_reg += ufbuf[d] * ns[d];
    }
    {
        __half2 hd = __float2half2_rn(lp_reg);
        lp2[tid] = *(unsigned*)&hd;
    }
    __syncthreads();
    asm volatile("barrier.cluster.arrive.aligned;" ::: "memory");
    asm volatile("barrier.cluster.wait.aligned;" ::: "memory");

    const int w = tid >> 5, l = tid & 31;
    const int kg  = (w & 1) * 32 + l;      // 0..63: group of 8 k-cols
    const int jq  = w >> 1;                // 0..7 : chunk of 32 local j
    const uint2* mp = (const uint2*)(mq + kg * KGS) + jq * 32;
    const float INV = 1.0f / 393216.0f;    // 1/(1536*256)

    for (int s = 0; s < TT - 1; ++s) {
        const int p = s & 1;
        const int skill = skl_s[s];

        // skill-column prefetch (threads 448..511), overlapped with GEMV
        float skv = 0.f;
        if (tid >= 448) skv = __ldg(nemb + skill * 64 + (tid - 448));

        // phase 1: base + temporal (node tid), next nlf
        float bse = 0.f, nn2 = 0.f;
#pragma unroll
        for (int d = 0; d < 32; d++) {
            bse += ubuf[p * 32 + d] * nr[d];
            nn2 += ufbuf[p * 32 + d] * ns[d];
        }
        const float bt = bse + __expf(-del_s[s] * 0.1f * nlf_reg) * lp_reg;
        nlf_reg = nn2;

        // partial GEMV over local j-chunk (32 rows x 8 cols, fp8 * half2)
        {
            __half2 a0 = __float2half2_rn(0.f), a1 = a0, a2 = a0, a3 = a0;
            const unsigned* lpj = lp2 + p * 512 + rank * 256 + jq * 32;
#pragma unroll 8
            for (int jj = 0; jj < 32; ++jj) {
                uint2 mv = mp[jj];
                unsigned lv = lpj[jj];
                __half2 l2 = *(__half2*)&lv;
                __half2 m0, m1, m2, m3;
                fp8x8_to_h2(mv.x, mv.y, m0, m1, m2, m3);
                a0 = __hfma2(m0, l2, a0);
                a1 = __hfma2(m1, l2, a1);
                a2 = __hfma2(m2, l2, a2);
                a3 = __hfma2(m3, l2, a3);
            }
            float2 f0 = __half22float2(a0), f1 = __half22float2(a1);
            float2 f2 = __half22float2(a2), f3 = __half22float2(a3);
            float* pd = parts + jq * 512 + kg * 8;
            *(float4*)(pd)     = make_float4(f0.x, f0.y, f1.x, f1.y);
            *(float4*)(pd + 4) = make_float4(f2.x, f2.y, f3.x, f3.y);
        }
        if (tid >= 448) skc[tid - 448] = skv;
        __syncthreads();

        // reduce own partials, push to peer, arrive
        float pl = 0.f;
#pragma unroll
        for (int q = 0; q < 8; q++) pl += parts[q * 512 + tid];
        asm volatile("st.shared::cluster.f32 [%0], %1;"
                     :: "r"(r_pr + (unsigned)(p * 512 + tid) * 4), "f"(pl) : "memory");
        asm volatile("mbarrier.arrive.release.cluster.shared::cluster.b64 _, [%0];"
                     :: "r"(r_bar + (unsigned)p * 8) : "memory");

        // tiny MLP (warp 0) overlaps peer latency
        if (tid < 32) {
            const int o = tid;
            const float lab = lab_s[s];
            float hv = bias[o];
#pragma unroll
            for (int c = 0; c < 32; ++c) {
                float u0 = ubuf[p * 32 + c], u1 = ufbuf[p * 32 + c];
                float u4 = skc[c], u3 = skc[32 + c];
                const float* wv = w1t + c * 160 + o;
                hv += u0 * wv[0] + u1 * wv[32] + lab * wv[64] + u3 * wv[96] + u4 * wv[128];
            }
            hbuf[o] = fmaxf(hv, 0.f);
            __syncwarp();
            float uu = bias[32 + o];
#pragma unroll
            for (int i2 = 0; i2 < 32; i2++) uu += hbuf[i2] * w2t[i2 * 32 + o];
            uubuf[o] = uu;
            __syncwarp();
            float af = bias[64 + o], ab = bias[96 + o];
#pragma unroll
            for (int i2 = 0; i2 < 32; i2++) {
                float u = uubuf[i2];
                af += u * wft[i2 * 32 + o];
                ab += u * wbt[i2 * 32 + o];
            }
            ubuf[(p ^ 1) * 32 + o] = tanhf(ab);
            ufbuf[(p ^ 1) * 32 + o] = tanhf(af);
        }

        // wait peer partials, finish cur_perf
        bar_wait_acq(bar_a + (unsigned)p * 8, (unsigned)((s >> 1) & 1));
        const float sp = (pl + partR[p * 512 + tid]) * INV;
        const float cur = 1.0f / (1.0f + __expf(-(bt + sp)));
        lp_reg = cur;
        __half2 cd = __float2half2_rn(cur);
        lp2[(p ^ 1) * 512 + tid] = *(unsigned*)&cd;
        if (rank == 0 && tid == skill) out[s * BSZ + b] = cur;
        __syncthreads();
    }
    asm volatile("barrier.cluster.arrive.aligned;" ::: "memory");
    asm volatile("barrier.cluster.wait.aligned;" ::: "memory");
}

// ---------------------------------------------------------------------------
extern "C" void kernel_launch(void* const* d_in, const int* in_sizes, int n_in,
                              void* d_out, int out_size) {
    const int*   skills = (const int*)  d_in[0];
    const int*   times_ = (const int*)  d_in[1];
    const float* labels = (const float*)d_in[2];
    const float* adj    = (const float*)d_in[3];
    const float* nemb   = (const float*)d_in[4];
    const float* ub0    = (const float*)d_in[5];
    const float* uf0    = (const float*)d_in[6];
    const float* cw1    = (const float*)d_in[7];
    const float* cb1    = (const float*)d_in[8];
    const float* cw2    = (const float*)d_in[9];
    const float* cb2    = (const float*)d_in[10];
    const float* lfw    = (const float*)d_in[11];
    const float* lfb    = (const float*)d_in[12];
    const float* lbw    = (const float*)d_in[13];
    const float* lbb    = (const float*)d_in[14];

    void *pP = nullptr, *pQ = nullptr, *pM = nullptr;
    cudaGetSymbolAddress(&pP, g_P);
    cudaGetSymbolAddress(&pQ, g_Q);
    cudaGetSymbolAddress(&pM, g_M);
    __nv_bfloat16* P = (__nv_bfloat16*)pP;
    __nv_bfloat16* Q = (__nv_bfloat16*)pQ;
    __nv_bfloat16* M = (__nv_bfloat16*)pM;

    cudaFuncSetAttribute(k_gemm, cudaFuncAttributeMaxDynamicSharedMemorySize, 65536);
    cudaFuncSetAttribute(k_scan, cudaFuncAttributeMaxDynamicSharedMemorySize, SCAN_SMEM);

    k_convert<<<16384, 256>>>(adj, P);
    dim3 g(4, 4, 64);
    k_gemm<<<g, 256, 65536>>>(P, P, Q);
    k_gemm<<<g, 256, 65536>>>(Q, P, M);
    k_add<<<16384, 256>>>(M, P, Q);
    k_scan<<<2 * BSZ, 512, SCAN_SMEM>>>(skills, times_, labels, nemb, ub0, uf0,
                                        cw1, cb1, cw2, cb2, lfw, lfb, lbw, lbb,
                                        M, (float*)d_out);
}

// round 4
// speedup vs baseline: 1.5902x; 1.1367x over previous
#include <cuda_runtime.h>
#include <cuda_bf16.h>
#include <cuda_fp16.h>
#include <mma.h>
using namespace nvcuda;

#define NN  512
#define BSZ 64
#define TT  200

static constexpr size_t MAT = (size_t)BSZ * NN * NN;
__device__ __nv_bfloat16 g_P[MAT];
__device__ __nv_bfloat16 g_Q[MAT];
__device__ __nv_bfloat16 g_M[MAT];

// ---------------------------------------------------------------------------
__global__ void k_convert(const float* __restrict__ adj, __nv_bfloat16* __restrict__ P) {
    size_t i = ((size_t)blockIdx.x * blockDim.x + threadIdx.x) * 4;
    float4 v = *(const float4*)(adj + i);
    const float s = 1.0f / 512.0f;
    __nv_bfloat162 p0 = __floats2bfloat162_rn(v.x * s, v.y * s);
    __nv_bfloat162 p1 = __floats2bfloat162_rn(v.z * s, v.w * s);
    uint2 u; u.x = *(unsigned*)&p0; u.y = *(unsigned*)&p1;
    *(uint2*)(P + i) = u;
}

__device__ __forceinline__ float2 bf2f2(unsigned u) {
    __nv_bfloat162 h = *(__nv_bfloat162*)&u;
    return make_float2(__low2float(h), __high2float(h));
}

__device__ __forceinline__ void cp16(void* s, const void* g) {
    unsigned sa = (unsigned)__cvta_generic_to_shared(s);
    asm volatile("cp.async.cg.shared.global [%0], [%1], 16;\n" :: "r"(sa), "l"(g));
}

// Batched bf16 GEMM; optional fused epilogue C = A@B + addA + addB
__global__ void __launch_bounds__(256) k_gemm(const __nv_bfloat16* __restrict__ A,
                                              const __nv_bfloat16* __restrict__ B,
                                              __nv_bfloat16* __restrict__ C,
                                              const __nv_bfloat16* __restrict__ addA,
                                              const __nv_bfloat16* __restrict__ addB) {
    extern __shared__ __nv_bfloat16 smg[];
    __nv_bfloat16* As = smg;
    __nv_bfloat16* Bs = smg + 2 * 128 * 64;
    const int tid = threadIdx.x, b = blockIdx.z;
    const int bm0 = blockIdx.y * 128, bn0 = blockIdx.x * 128;
    const __nv_bfloat16* Ab = A + (size_t)b * NN * NN;
    const __nv_bfloat16* Bb = B + (size_t)b * NN * NN;
    const int ar = tid >> 3, ac = (tid & 7) * 8;
    const int br = tid >> 4, bc = (tid & 15) * 8;
    auto load_tiles = [&](int st, int k0) {
        __nv_bfloat16* a = As + st * 8192;
        __nv_bfloat16* bt = Bs + st * 8192;
#pragma unroll
        for (int rr = 0; rr < 128; rr += 32)
            cp16(a + (ar + rr) * 64 + ac, Ab + (size_t)(bm0 + ar + rr) * NN + k0 + ac);
#pragma unroll
        for (int rr = 0; rr < 64; rr += 16)
            cp16(bt + (br + rr) * 128 + bc, Bb + (size_t)(k0 + br + rr) * NN + bn0 + bc);
        asm volatile("cp.async.commit_group;\n");
    };
    const int w = tid >> 5, wm = w >> 1, wn = w & 1;
    wmma::fragment<wmma::accumulator, 16, 16, 16, float> cf[2][4];
#pragma unroll
    for (int i = 0; i < 2; i++)
#pragma unroll
        for (int j = 0; j < 4; j++) wmma::fill_fragment(cf[i][j], 0.0f);
    load_tiles(0, 0);
#pragma unroll
    for (int kt = 0; kt < 8; ++kt) {
        asm volatile("cp.async.wait_group 0;\n");
        __syncthreads();
        if (kt < 7) load_tiles((kt + 1) & 1, (kt + 1) * 64);
        const __nv_bfloat16* a = As + (kt & 1) * 8192;
        const __nv_bfloat16* bt = Bs + (kt & 1) * 8192;
#pragma unroll
        for (int kk = 0; kk < 4; ++kk) {
            wmma::fragment<wmma::matrix_a, 16, 16, 16, __nv_bfloat16, wmma::row_major> af[2];
            wmma::fragment<wmma::matrix_b, 16, 16, 16, __nv_bfloat16, wmma::row_major> bfr[4];
#pragma unroll
            for (int i = 0; i < 2; i++)
                wmma::load_matrix_sync(af[i], a + (wm * 32 + i * 16) * 64 + kk * 16, 64);
#pragma unroll
            for (int j = 0; j < 4; j++)
                wmma::load_matrix_sync(bfr[j], bt + (kk * 16) * 128 + wn * 64 + j * 16, 128);
#pragma unroll
            for (int i = 0; i < 2; i++)
#pragma unroll
                for (int j = 0; j < 4; j++)
                    wmma::mma_sync(cf[i][j], af[i], bfr[j], cf[i][j]);
        }
        __syncthreads();
    }
    float* Cs = (float*)smg;
#pragma unroll
    for (int i = 0; i < 2; i++)
#pragma unroll
        for (int j = 0; j < 4; j++)
            wmma::store_matrix_sync(Cs + (wm * 32 + i * 16) * 128 + wn * 64 + j * 16,
                                    cf[i][j], 128, wmma::mem_row_major);
    __syncthreads();
    int rl = tid >> 1, half = tid & 1;
    size_t goff = (size_t)b * NN * NN + (size_t)(bm0 + rl) * NN + bn0 + half * 64;
    __nv_bfloat16* Cg = C + goff;
    const float* src = Cs + rl * 128 + half * 64;
#pragma unroll
    for (int c = 0; c < 64; c += 4) {
        float4 v = *(const float4*)(src + c);
        if (addA) {
            uint2 pa = *(const uint2*)(addA + goff + c);
            uint2 qa = *(const uint2*)(addB + goff + c);
            float2 a0 = bf2f2(pa.x), a1 = bf2f2(pa.y);
            float2 b0 = bf2f2(qa.x), b1 = bf2f2(qa.y);
            v.x += a0.x + b0.x; v.y += a0.y + b0.y;
            v.z += a1.x + b1.x; v.w += a1.y + b1.y;
        }
        __nv_bfloat162 p0 = __floats2bfloat162_rn(v.x, v.y);
        __nv_bfloat162 p1 = __floats2bfloat162_rn(v.z, v.w);
        uint2 u; u.x = *(unsigned*)&p0; u.y = *(unsigned*)&p1;
        *(uint2*)(Cg + c) = u;
    }
}

// ---------------------------------------------------------------------------
// Cluster scan: 2 CTAs/batch, 640 threads (16 main warps + 4 MLP warps).
// M^T int8 SMEM-resident (j-split), DP4A GEMV, f32x2 dots, overlapped MLP.
// ---------------------------------------------------------------------------
#define MROW 272                    // 256 data bytes + 16 pad
#define OFF_MQ     0                // 512*272 = 139264
#define OFF_LPQ    139264           // int8[2][256]
#define OFF_PARTR  139776           // float[2][512]
#define OFF_W1     143872           // float[160][32]
#define OFF_W2     164352
#define OFF_WF     168448
#define OFF_WB     172544
#define OFF_BIAS   176640           // 128 floats
#define OFF_UB     177152           // float[2][32]
#define OFF_UF     177408
#define OFF_H      177664           // float[32]
#define OFF_UU     177792
#define OFF_MLPP   177920           // float[4][32]
#define OFF_SKC    178432           // float[64]
#define OFF_DEL    178688           // float[200]
#define OFF_LAB    179488
#define OFF_SKL    180288
#define OFF_BAR    181088           // 2 mbarriers
#define SCAN_SMEM  181120

#define QM   21675.0f
#define QL0  7.0f
#define QL1  127.0f

__device__ __forceinline__ unsigned smem_u32(const void* p) {
    unsigned r;
    asm("{ .reg .u64 t; cvta.to.shared.u64 t, %1; cvt.u32.u64 %0, t; }" : "=r"(r) : "l"(p));
    return r;
}
__device__ __forceinline__ unsigned mapa_u32(unsigned a, unsigned rank) {
    unsigned r;
    asm("mapa.shared::cluster.u32 %0, %1, %2;" : "=r"(r) : "r"(a), "r"(rank));
    return r;
}
__device__ __forceinline__ void bar_wait_acq(unsigned a, unsigned parity) {
    unsigned done;
    asm volatile("{\n\t.reg .pred p;\n\t"
        "mbarrier.try_wait.parity.acquire.cluster.shared::cta.b64 p, [%1], %2;\n\t"
        "selp.b32 %0, 1, 0, p;\n\t}" : "=r"(done) : "r"(a), "r"(parity) : "memory");
    while (!done)
        asm volatile("{\n\t.reg .pred p;\n\t"
            "mbarrier.try_wait.parity.acquire.cluster.shared::cta.b64 p, [%1], %2, 0x989680;\n\t"
            "selp.b32 %0, 1, 0, p;\n\t}" : "=r"(done) : "r"(a), "r"(parity) : "memory");
}
__device__ __forceinline__ unsigned long long packf2(float lo, float hi) {
    unsigned long long r;
    asm("mov.b64 %0, {%1, %2};" : "=l"(r) : "f"(lo), "f"(hi));
    return r;
}
__device__ __forceinline__ void fma_x2(unsigned long long& acc, unsigned long long a, unsigned long long b) {
    asm("fma.rn.f32x2 %0, %1, %2, %0;" : "+l"(acc) : "l"(a), "l"(b));
}
__device__ __forceinline__ float2 unpackf2(unsigned long long v) {
    float lo, hi;
    asm("mov.b64 {%0, %1}, %2;" : "=f"(lo), "=f"(hi) : "l"(v));
    return make_float2(lo, hi);
}
#define BAR1() asm volatile("bar.sync 1, 128;" ::: "memory")

__global__ void __launch_bounds__(640, 1) __cluster_dims__(2, 1, 1)
k_scan(const int* __restrict__ skills, const int* __restrict__ times_,
       const float* __restrict__ labels, const float* __restrict__ nemb,
       const float* __restrict__ ub0, const float* __restrict__ uf0,
       const float* __restrict__ cw1, const float* __restrict__ cb1,
       const float* __restrict__ cw2, const float* __restrict__ cb2,
       const float* __restrict__ lfw, const float* __restrict__ lfb,
       const float* __restrict__ lbw, const float* __restrict__ lbb,
       const __nv_bfloat16* __restrict__ Mg, float* __restrict__ out) {

    extern __shared__ char smb[];
    char*     mq    = smb + OFF_MQ;
    char*     lpq   = smb + OFF_LPQ;
    float*    partR = (float*)(smb + OFF_PARTR);
    float*    w1t   = (float*)(smb + OFF_W1);
    float*    w2t   = (float*)(smb + OFF_W2);
    float*    wft   = (float*)(smb + OFF_WF);
    float*    wbt   = (float*)(smb + OFF_WB);
    float*    bias  = (float*)(smb + OFF_BIAS);
    float*    ubuf  = (float*)(smb + OFF_UB);
    float*    ufbuf = (float*)(smb + OFF_UF);
    float*    hbuf  = (float*)(smb + OFF_H);
    float*    uubuf = (float*)(smb + OFF_UU);
    float*    mlpp  = (float*)(smb + OFF_MLPP);
    float*    skc   = (float*)(smb + OFF_SKC);
    float*    del_s = (float*)(smb + OFF_DEL);
    float*    lab_s = (float*)(smb + OFF_LAB);
    int*      skl_s = (int*)(smb + OFF_SKL);

    const int tid = threadIdx.x;
    const int b = blockIdx.x >> 1;
    unsigned rank;
    asm("mov.u32 %0, %%cluster_ctarank;" : "=r"(rank));
    const unsigned peer = rank ^ 1;

    const unsigned sbase = smem_u32(smb);
    const unsigned bar_a = sbase + OFF_BAR;
    const unsigned r_pr  = mapa_u32(sbase + OFF_PARTR, peer);
    const unsigned r_bar = mapa_u32(bar_a, peer);

    if (tid == 0) {
        asm volatile("mbarrier.init.shared.b64 [%0], 512;" :: "r"(bar_a) : "memory");
        asm volatile("mbarrier.init.shared.b64 [%0], 512;" :: "r"(bar_a + 8) : "memory");
    }

    for (int i = tid; i < 5120; i += 640) { int o = i / 160, r = i % 160; w1t[r * 32 + o] = cw1[i]; }
    for (int i = tid; i < 1024; i += 640) {
        int o = i >> 5, r = i & 31;
        w2t[r * 32 + o] = cw2[i]; wft[r * 32 + o] = lfw[i]; wbt[r * 32 + o] = lbw[i];
    }
    if (tid < 32) {
        bias[tid] = cb1[tid]; bias[32 + tid] = cb2[tid];
        bias[64 + tid] = lfb[tid]; bias[96 + tid] = lbb[tid];
        ubuf[tid] = ub0[b * 32 + tid]; ufbuf[tid] = uf0[b * 32 + tid];
    }
    const float invlog5 = 0.6213349345596119f;
    for (int s = tid; s < TT - 1; s += 640) {
        float dtv = fabsf((float)(times_[b * TT + s + 1] - times_[b * TT + s]));
        del_s[s] = logf(dtv + 1e-6f) * invlog5;
        lab_s[s] = labels[b * TT + s + 1];
        skl_s[s] = skills[b * TT + s + 1];
    }

    // node-embedding pairs in registers (main threads only; node = tid)
    unsigned long long nr2[16], ns2[16];
    if (tid < 512) {
#pragma unroll
        for (int i = 0; i < 16; i++) {
            float2 s2 = *(const float2*)(nemb + tid * 64 + 2 * i);
            float2 r2 = *(const float2*)(nemb + tid * 64 + 32 + 2 * i);
            ns2[i] = packf2(s2.x, s2.y);
            nr2[i] = packf2(r2.x, r2.y);
        }
    }

    // int8 M^T fill: Mt[k][jloc] = round(M[rank*256+jloc][k] * QM)
    {
        const __nv_bfloat16* Mb = Mg + ((size_t)b << 18) + (size_t)(rank * 256) * NN;
        for (int pi = tid; pi < 16384; pi += 640) {
            int j = pi >> 6, kg = (pi & 63) * 8;
            uint4 v = *(const uint4*)(Mb + (size_t)j * NN + kg);
            float2 f0 = bf2f2(v.x), f1 = bf2f2(v.y), f2 = bf2f2(v.z), f3 = bf2f2(v.w);
            float vals[8] = {f0.x, f0.y, f1.x, f1.y, f2.x, f2.y, f3.x, f3.y};
#pragma unroll
            for (int e = 0; e < 8; e++) {
                int q = __float2int_rn(vals[e] * QM);
                q = min(q, 127);
                mq[(kg + e) * MROW + j] = (char)q;
            }
        }
    }
    __syncthreads();

    // initial carry
    float lp_reg = 0.f, nlf_reg = 0.f;
    if (tid < 512) {
#pragma unroll
        for (int d = 0; d < 32; d++) {
            lp_reg  += ubuf[d] * nemb[tid * 64 + 32 + d];
            nlf_reg += ufbuf[d] * nemb[tid * 64 + d];
        }
        if ((tid >> 8) == (int)rank) {
            int q = __float2int_rn(lp_reg * QL0);
            q = max(min(q, 127), -127);
            lpq[tid - rank * 256] = (char)q;
        }
    }
    __syncthreads();
    asm volatile("barrier.cluster.arrive.aligned;" ::: "memory");
    asm volatile("barrier.cluster.wait.aligned;" ::: "memory");

    const float INV0 = 1.0f / (QM * QL0 * 1536.0f);
    const float INV1 = 1.0f / (QM * QL1 * 1536.0f);

    for (int s = 0; s < TT - 1; ++s) {
        const int p = s & 1;
        const unsigned parity = (unsigned)((s >> 1) & 1);
        const int skill = skl_s[s];

        if (tid < 512) {
            // phase 1: base + temporal, next nlf (f32x2 packed FMA)
            unsigned long long aB = 0ull, aN = 0ull;
            const float2* u2 = (const float2*)(ubuf + p * 32);
            const float2* f2 = (const float2*)(ufbuf + p * 32);
#pragma unroll
            for (int i = 0; i < 16; i++) {
                float2 uu2 = u2[i], ff2 = f2[i];
                fma_x2(aB, packf2(uu2.x, uu2.y), nr2[i]);
                fma_x2(aN, packf2(ff2.x, ff2.y), ns2[i]);
            }
            float2 rb = unpackf2(aB), rn = unpackf2(aN);
            const float bt = rb.x + rb.y + __expf(-del_s[s] * 0.1f * nlf_reg) * lp_reg;
            nlf_reg = rn.x + rn.y;

            // DP4A GEMV: thread owns column k=tid over local j-half
            int acc = 0;
            const int4* mp4 = (const int4*)(mq + tid * MROW);
            const int4* lp4 = (const int4*)(lpq + p * 256);
#pragma unroll
            for (int i = 0; i < 16; i++) {
                int4 mv = mp4[i];
                int4 lv = lp4[i];
                acc = __dp4a(mv.x, lv.x, acc);
                acc = __dp4a(mv.y, lv.y, acc);
                acc = __dp4a(mv.z, lv.z, acc);
                acc = __dp4a(mv.w, lv.w, acc);
            }
            const float pl = (float)acc;

            // push partial to peer, arrive
            asm volatile("st.shared::cluster.f32 [%0], %1;"
                         :: "r"(r_pr + (unsigned)(p * 512 + tid) * 4), "f"(pl) : "memory");
            asm volatile("mbarrier.arrive.release.cluster.shared::cluster.b64 _, [%0];"
                         :: "r"(r_bar + (unsigned)p * 8) : "memory");

            // wait peer half, finish
            bar_wait_acq(bar_a + (unsigned)p * 8, parity);
            const float INVs = (s == 0) ? INV0 : INV1;
            const float x = bt + (pl + partR[p * 512 + tid]) * INVs;
            const float cur = 1.0f / (1.0f + __expf(-x));
            lp_reg = cur;
            if ((tid >> 8) == (int)rank) {
                int q = __float2int_rn(cur * QL1);
                lpq[(p ^ 1) * 256 + (tid - rank * 256)] = (char)q;
            }
            if (rank == 0 && tid == skill) out[s * BSZ + b] = cur;
        } else {
            // MLP warps (m = tid-512 in [0,128))
            const int m = tid - 512;
            const int o = m & 31;
            const float lab = lab_s[s];
            if (m < 64) skc[m] = __ldg(nemb + skill * 64 + m);
            BAR1();
            {   // conv1 partials: c in [q*8, q*8+8)
                const int q = m >> 5;
                float hp = 0.f;
#pragma unroll
                for (int cc = 0; cc < 8; cc++) {
                    const int c = q * 8 + cc;
                    const float u0 = ubuf[p * 32 + c], u1 = ufbuf[p * 32 + c];
                    const float u3 = skc[32 + c], u4 = skc[c];
                    const float* wv = w1t + c * 160 + o;
                    hp += u0 * wv[0] + u1 * wv[32] + lab * wv[64] + u3 * wv[96] + u4 * wv[128];
                }
                mlpp[q * 32 + o] = hp;
            }
            BAR1();
            if (m < 32) hbuf[o] = fmaxf(bias[o] + mlpp[o] + mlpp[32 + o] + mlpp[64 + o] + mlpp[96 + o], 0.f);
            BAR1();
            {   // conv2 partials
                const int q = m >> 5;
                float up = 0.f;
#pragma unroll
                for (int ii = 0; ii < 8; ii++) {
                    const int i2 = q * 8 + ii;
                    up += hbuf[i2] * w2t[i2 * 32 + o];
                }
                mlpp[q * 32 + o] = up;
            }
            BAR1();
            if (m < 32) uubuf[o] = bias[32 + o] + mlpp[o] + mlpp[32 + o] + mlpp[64 + o] + mlpp[96 + o];
            BAR1();
            {   // lin_f (warps 16-17) / lin_b (warps 18-19) partials
                float ap = 0.f;
                if (m < 64) {
                    const int q2 = m >> 5;
#pragma unroll
                    for (int ii = 0; ii < 16; ii++) {
                        const int i2 = q2 * 16 + ii;
                        ap += uubuf[i2] * wft[i2 * 32 + o];
                    }
                    mlpp[q2 * 32 + o] = ap;
                } else {
                    const int q2 = (m - 64) >> 5;
#pragma unroll
                    for (int ii = 0; ii < 16; ii++) {
                        const int i2 = q2 * 16 + ii;
                        ap += uubuf[i2] * wbt[i2 * 32 + o];
                    }
                    mlpp[64 + q2 * 32 + o] = ap;
                }
            }
            BAR1();
            if (m < 32) {
                ufbuf[(p ^ 1) * 32 + o] = tanhf(bias[64 + o] + mlpp[o] + mlpp[32 + o]);
                ubuf[(p ^ 1) * 32 + o]  = tanhf(bias[96 + o] + mlpp[64 + o] + mlpp[96 + o]);
            }
        }
        __syncthreads();
    }
    asm volatile("barrier.cluster.arrive.aligned;" ::: "memory");
    asm volatile("barrier.cluster.wait.aligned;" ::: "memory");
}

// ---------------------------------------------------------------------------
extern "C" void kernel_launch(void* const* d_in, const int* in_sizes, int n_in,
                              void* d_out, int out_size) {
    const int*   skills = (const int*)  d_in[0];
    const int*   times_ = (const int*)  d_in[1];
    const float* labels = (const float*)d_in[2];
    const float* adj    = (const float*)d_in[3];
    const float* nemb   = (const float*)d_in[4];
    const float* ub0    = (const float*)d_in[5];
    const float* uf0    = (const float*)d_in[6];
    const float* cw1    = (const float*)d_in[7];
    const float* cb1    = (const float*)d_in[8];
    const float* cw2    = (const float*)d_in[9];
    const float* cb2    = (const float*)d_in[10];
    const float* lfw    = (const float*)d_in[11];
    const float* lfb    = (const float*)d_in[12];
    const float* lbw    = (const float*)d_in[13];
    const float* lbb    = (const float*)d_in[14];

    void *pP = nullptr, *pQ = nullptr, *pM = nullptr;
    cudaGetSymbolAddress(&pP, g_P);
    cudaGetSymbolAddress(&pQ, g_Q);
    cudaGetSymbolAddress(&pM, g_M);
    __nv_bfloat16* P = (__nv_bfloat16*)pP;
    __nv_bfloat16* Q = (__nv_bfloat16*)pQ;
    __nv_bfloat16* M = (__nv_bfloat16*)pM;

    cudaFuncSetAttribute(k_gemm, cudaFuncAttributeMaxDynamicSharedMemorySize, 65536);
    cudaFuncSetAttribute(k_scan, cudaFuncAttributeMaxDynamicSharedMemorySize, SCAN_SMEM);

    k_convert<<<16384, 256>>>(adj, P);
    dim3 g(4, 4, 64);
    k_gemm<<<g, 256, 65536>>>(P, P, Q, nullptr, nullptr);
    k_gemm<<<g, 256, 65536>>>(Q, P, M, P, Q);     // M = Q@P + P + Q
    k_scan<<<2 * BSZ, 640, SCAN_SMEM>>>(skills, times_, labels, nemb, ub0, uf0,
                                        cw1, cb1, cw2, cb2, lfw, lfb, lbw, lbb,
                                        M, (float*)d_out);
}

// round 5
// speedup vs baseline: 2.3773x; 1.4950x over previous
#include <cuda_runtime.h>
#include <cuda_bf16.h>
#include <cuda_fp16.h>
#include <mma.h>
using namespace nvcuda;

#define NN  512
#define BSZ 64
#define TT  200

static constexpr size_t MAT = (size_t)BSZ * NN * NN;
__device__ __nv_bfloat16 g_P[MAT];
__device__ __nv_bfloat16 g_Q[MAT];
__device__ __nv_bfloat16 g_M[MAT];

// ---------------------------------------------------------------------------
__global__ void k_convert(const float* __restrict__ adj, __nv_bfloat16* __restrict__ P) {
    size_t i = ((size_t)blockIdx.x * blockDim.x + threadIdx.x) * 4;
    float4 v = *(const float4*)(adj + i);
    const float s = 1.0f / 512.0f;
    __nv_bfloat162 p0 = __floats2bfloat162_rn(v.x * s, v.y * s);
    __nv_bfloat162 p1 = __floats2bfloat162_rn(v.z * s, v.w * s);
    uint2 u; u.x = *(unsigned*)&p0; u.y = *(unsigned*)&p1;
    *(uint2*)(P + i) = u;
}

__device__ __forceinline__ float2 bf2f2(unsigned u) {
    __nv_bfloat162 h = *(__nv_bfloat162*)&u;
    return make_float2(__low2float(h), __high2float(h));
}

__device__ __forceinline__ void cp16(void* s, const void* g) {
    unsigned sa = (unsigned)__cvta_generic_to_shared(s);
    asm volatile("cp.async.cg.shared.global [%0], [%1], 16;\n" :: "r"(sa), "l"(g));
}

// Batched bf16 GEMM; optional fused epilogue C = A@B + addA + addB
// Padded smem tiles: A stride 72, B stride 136 -> conflict-free ldmatrix.
#define AST 72
#define BST 136
#define A_STAGE (128 * AST)
#define B_STAGE (64 * BST)
#define GEMM_SMEM ((2 * A_STAGE + 2 * B_STAGE) * 2)

__global__ void __launch_bounds__(256) k_gemm(const __nv_bfloat16* __restrict__ A,
                                              const __nv_bfloat16* __restrict__ B,
                                              __nv_bfloat16* __restrict__ C,
                                              const __nv_bfloat16* __restrict__ addA,
                                              const __nv_bfloat16* __restrict__ addB) {
    extern __shared__ __nv_bfloat16 smg[];
    __nv_bfloat16* As = smg;
    __nv_bfloat16* Bs = smg + 2 * A_STAGE;
    const int tid = threadIdx.x, b = blockIdx.z;
    const int bm0 = blockIdx.y * 128, bn0 = blockIdx.x * 128;
    const __nv_bfloat16* Ab = A + (size_t)b * NN * NN;
    const __nv_bfloat16* Bb = B + (size_t)b * NN * NN;
    const int ar = tid >> 3, ac = (tid & 7) * 8;
    const int br = tid >> 4, bc = (tid & 15) * 8;
    auto load_tiles = [&](int st, int k0) {
        __nv_bfloat16* a = As + st * A_STAGE;
        __nv_bfloat16* bt = Bs + st * B_STAGE;
#pragma unroll
        for (int rr = 0; rr < 128; rr += 32)
            cp16(a + (ar + rr) * AST + ac, Ab + (size_t)(bm0 + ar + rr) * NN + k0 + ac);
#pragma unroll
        for (int rr = 0; rr < 64; rr += 16)
            cp16(bt + (br + rr) * BST + bc, Bb + (size_t)(k0 + br + rr) * NN + bn0 + bc);
        asm volatile("cp.async.commit_group;\n");
    };
    const int w = tid >> 5, wm = w >> 1, wn = w & 1;
    wmma::fragment<wmma::accumulator, 16, 16, 16, float> cf[2][4];
#pragma unroll
    for (int i = 0; i < 2; i++)
#pragma unroll
        for (int j = 0; j < 4; j++) wmma::fill_fragment(cf[i][j], 0.0f);
    load_tiles(0, 0);
#pragma unroll
    for (int kt = 0; kt < 8; ++kt) {
        asm volatile("cp.async.wait_group 0;\n");
        __syncthreads();
        if (kt < 7) load_tiles((kt + 1) & 1, (kt + 1) * 64);
        const __nv_bfloat16* a = As + (kt & 1) * A_STAGE;
        const __nv_bfloat16* bt = Bs + (kt & 1) * B_STAGE;
#pragma unroll
        for (int kk = 0; kk < 4; ++kk) {
            wmma::fragment<wmma::matrix_a, 16, 16, 16, __nv_bfloat16, wmma::row_major> af[2];
            wmma::fragment<wmma::matrix_b, 16, 16, 16, __nv_bfloat16, wmma::row_major> bfr[4];
#pragma unroll
            for (int i = 0; i < 2; i++)
                wmma::load_matrix_sync(af[i], a + (wm * 32 + i * 16) * AST + kk * 16, AST);
#pragma unroll
            for (int j = 0; j < 4; j++)
                wmma::load_matrix_sync(bfr[j], bt + (kk * 16) * BST + wn * 64 + j * 16, BST);
#pragma unroll
            for (int i = 0; i < 2; i++)
#pragma unroll
                for (int j = 0; j < 4; j++)
                    wmma::mma_sync(cf[i][j], af[i], bfr[j], cf[i][j]);
        }
        __syncthreads();
    }
    float* Cs = (float*)smg;   // 128 x 132 floats
#pragma unroll
    for (int i = 0; i < 2; i++)
#pragma unroll
        for (int j = 0; j < 4; j++)
            wmma::store_matrix_sync(Cs + (wm * 32 + i * 16) * 132 + wn * 64 + j * 16,
                                    cf[i][j], 132, wmma::mem_row_major);
    __syncthreads();
    int rl = tid >> 1, half = tid & 1;
    size_t goff = (size_t)b * NN * NN + (size_t)(bm0 + rl) * NN + bn0 + half * 64;
    __nv_bfloat16* Cg = C + goff;
    const float* src = Cs + rl * 132 + half * 64;
#pragma unroll
    for (int c = 0; c < 64; c += 4) {
        float4 v = *(const float4*)(src + c);
        if (addA) {
            uint2 pa = *(const uint2*)(addA + goff + c);
            uint2 qa = *(const uint2*)(addB + goff + c);
            float2 a0 = bf2f2(pa.x), a1 = bf2f2(pa.y);
            float2 b0 = bf2f2(qa.x), b1 = bf2f2(qa.y);
            v.x += a0.x + b0.x; v.y += a0.y + b0.y;
            v.z += a1.x + b1.x; v.w += a1.y + b1.y;
        }
        __nv_bfloat162 p0 = __floats2bfloat162_rn(v.x, v.y);
        __nv_bfloat162 p1 = __floats2bfloat162_rn(v.z, v.w);
        uint2 u; u.x = *(unsigned*)&p0; u.y = *(unsigned*)&p1;
        *(uint2*)(Cg + c) = u;
    }
}

// ---------------------------------------------------------------------------
// Cluster scan: 2 CTAs/batch, 640 threads (16 main warps + 4 MLP warps).
// M^T int8 SMEM-resident (j-split), DP4A GEMV, st.async tx-counted exchange.
// ---------------------------------------------------------------------------
#define MROW 272
#define OFF_MQ     0                // 512*272 = 139264
#define OFF_LPQ    139264           // int8[2][256]
#define OFF_PARTR  139776           // float[2][512]
#define OFF_W1     143872           // float[160][32]
#define OFF_W2     164352
#define OFF_WF     168448
#define OFF_WB     172544
#define OFF_BIAS   176640
#define OFF_UB     177152
#define OFF_UF     177408
#define OFF_H      177664
#define OFF_UU     177792
#define OFF_MLPP   177920
#define OFF_SKC    178432
#define OFF_DEL    178688
#define OFF_LAB    179488
#define OFF_SKL    180288
#define OFF_BAR    181088           // 2 mbarriers
#define SCAN_SMEM  181120

#define QM   21675.0f
#define QL0  7.0f
#define QL1  127.0f

__device__ __forceinline__ unsigned smem_u32(const void* p) {
    unsigned r;
    asm("{ .reg .u64 t; cvta.to.shared.u64 t, %1; cvt.u32.u64 %0, t; }" : "=r"(r) : "l"(p));
    return r;
}
__device__ __forceinline__ unsigned mapa_u32(unsigned a, unsigned rank) {
    unsigned r;
    asm("mapa.shared::cluster.u32 %0, %1, %2;" : "=r"(r) : "r"(a), "r"(rank));
    return r;
}
__device__ __forceinline__ void bar_wait_acq(unsigned a, unsigned parity) {
    unsigned done;
    asm volatile("{\n\t.reg .pred p;\n\t"
        "mbarrier.try_wait.parity.acquire.cluster.shared::cta.b64 p, [%1], %2;\n\t"
        "selp.b32 %0, 1, 0, p;\n\t}" : "=r"(done) : "r"(a), "r"(parity) : "memory");
    while (!done)
        asm volatile("{\n\t.reg .pred p;\n\t"
            "mbarrier.try_wait.parity.acquire.cluster.shared::cta.b64 p, [%1], %2, 0x989680;\n\t"
            "selp.b32 %0, 1, 0, p;\n\t}" : "=r"(done) : "r"(a), "r"(parity) : "memory");
}
__device__ __forceinline__ void expect_tx(unsigned bar, unsigned bytes) {
    asm volatile("mbarrier.arrive.expect_tx.shared.b64 _, [%0], %1;"
                 :: "r"(bar), "r"(bytes) : "memory");
}
__device__ __forceinline__ void st_async_v4(unsigned addr, float4 v, unsigned mbar) {
    asm volatile("st.async.weak.shared::cluster.mbarrier::complete_tx::bytes.v4.f32 "
                 "[%0], {%1, %2, %3, %4}, [%5];"
                 :: "r"(addr), "f"(v.x), "f"(v.y), "f"(v.z), "f"(v.w), "r"(mbar) : "memory");
}
__device__ __forceinline__ unsigned long long packf2(float lo, float hi) {
    unsigned long long r;
    asm("mov.b64 %0, {%1, %2};" : "=l"(r) : "f"(lo), "f"(hi));
    return r;
}
__device__ __forceinline__ void fma_x2(unsigned long long& acc, unsigned long long a, unsigned long long b) {
    asm("fma.rn.f32x2 %0, %1, %2, %0;" : "+l"(acc) : "l"(a), "l"(b));
}
__device__ __forceinline__ float2 unpackf2(unsigned long long v) {
    float lo, hi;
    asm("mov.b64 {%0, %1}, %2;" : "=f"(lo), "=f"(hi) : "l"(v));
    return make_float2(lo, hi);
}
#define BAR1() asm volatile("bar.sync 1, 128;" ::: "memory")

__global__ void __launch_bounds__(640, 1) __cluster_dims__(2, 1, 1)
k_scan(const int* __restrict__ skills, const int* __restrict__ times_,
       const float* __restrict__ labels, const float* __restrict__ nemb,
       const float* __restrict__ ub0, const float* __restrict__ uf0,
       const float* __restrict__ cw1, const float* __restrict__ cb1,
       const float* __restrict__ cw2, const float* __restrict__ cb2,
       const float* __restrict__ lfw, const float* __restrict__ lfb,
       const float* __restrict__ lbw, const float* __restrict__ lbb,
       const __nv_bfloat16* __restrict__ Mg, float* __restrict__ out) {

    extern __shared__ char smb[];
    char*     mq    = smb + OFF_MQ;
    char*     lpq   = smb + OFF_LPQ;
    float*    partR = (float*)(smb + OFF_PARTR);
    float*    w1t   = (float*)(smb + OFF_W1);
    float*    w2t   = (float*)(smb + OFF_W2);
    float*    wft   = (float*)(smb + OFF_WF);
    float*    wbt   = (float*)(smb + OFF_WB);
    float*    bias  = (float*)(smb + OFF_BIAS);
    float*    ubuf  = (float*)(smb + OFF_UB);
    float*    ufbuf = (float*)(smb + OFF_UF);
    float*    hbuf  = (float*)(smb + OFF_H);
    float*    uubuf = (float*)(smb + OFF_UU);
    float*    mlpp  = (float*)(smb + OFF_MLPP);
    float*    skc   = (float*)(smb + OFF_SKC);
    float*    del_s = (float*)(smb + OFF_DEL);
    float*    lab_s = (float*)(smb + OFF_LAB);
    int*      skl_s = (int*)(smb + OFF_SKL);

    const int tid = threadIdx.x;
    const int b = blockIdx.x >> 1;
    unsigned rank;
    asm("mov.u32 %0, %%cluster_ctarank;" : "=r"(rank));
    const unsigned peer = rank ^ 1;

    const unsigned sbase = smem_u32(smb);
    const unsigned bar_a = sbase + OFF_BAR;
    const unsigned r_pr  = mapa_u32(sbase + OFF_PARTR, peer);
    const unsigned r_bar = mapa_u32(bar_a, peer);

    if (tid == 0) {
        asm volatile("mbarrier.init.shared.b64 [%0], 1;" :: "r"(bar_a) : "memory");
        asm volatile("mbarrier.init.shared.b64 [%0], 1;" :: "r"(bar_a + 8) : "memory");
    }

    for (int i = tid; i < 5120; i += 640) { int o = i / 160, r = i % 160; w1t[r * 32 + o] = cw1[i]; }
    for (int i = tid; i < 1024; i += 640) {
        int o = i >> 5, r = i & 31;
        w2t[r * 32 + o] = cw2[i]; wft[r * 32 + o] = lfw[i]; wbt[r * 32 + o] = lbw[i];
    }
    if (tid < 32) {
        bias[tid] = cb1[tid]; bias[32 + tid] = cb2[tid];
        bias[64 + tid] = lfb[tid]; bias[96 + tid] = lbb[tid];
        ubuf[tid] = ub0[b * 32 + tid]; ufbuf[tid] = uf0[b * 32 + tid];
    }
    const float invlog5 = 0.6213349345596119f;
    for (int s = tid; s < TT - 1; s += 640) {
        float dtv = fabsf((float)(times_[b * TT + s + 1] - times_[b * TT + s]));
        del_s[s] = logf(dtv + 1e-6f) * invlog5;
        lab_s[s] = labels[b * TT + s + 1];
        skl_s[s] = skills[b * TT + s + 1];
    }

    unsigned long long nr2[16], ns2[16];
    if (tid < 512) {
#pragma unroll
        for (int i = 0; i < 16; i++) {
            float2 s2 = *(const float2*)(nemb + tid * 64 + 2 * i);
            float2 r2 = *(const float2*)(nemb + tid * 64 + 32 + 2 * i);
            ns2[i] = packf2(s2.x, s2.y);
            nr2[i] = packf2(r2.x, r2.y);
        }
    }

    // int8 M^T fill
    {
        const __nv_bfloat16* Mb = Mg + ((size_t)b << 18) + (size_t)(rank * 256) * NN;
        for (int pi = tid; pi < 16384; pi += 640) {
            int j = pi >> 6, kg = (pi & 63) * 8;
            uint4 v = *(const uint4*)(Mb + (size_t)j * NN + kg);
            float2 f0 = bf2f2(v.x), f1 = bf2f2(v.y), f2 = bf2f2(v.z), f3 = bf2f2(v.w);
            float vals[8] = {f0.x, f0.y, f1.x, f1.y, f2.x, f2.y, f3.x, f3.y};
#pragma unroll
            for (int e = 0; e < 8; e++) {
                int q = __float2int_rn(vals[e] * QM);
                q = min(q, 127);
                mq[(kg + e) * MROW + j] = (char)q;
            }
        }
    }
    __syncthreads();

    // initial carry
    float lp_reg = 0.f, nlf_reg = 0.f;
    if (tid < 512) {
#pragma unroll
        for (int d = 0; d < 32; d++) {
            lp_reg  += ubuf[d] * nemb[tid * 64 + 32 + d];
            nlf_reg += ufbuf[d] * nemb[tid * 64 + d];
        }
        if ((tid >> 8) == (int)rank) {
            int q = __float2int_rn(lp_reg * QL0);
            q = max(min(q, 127), -127);
            lpq[tid - rank * 256] = (char)q;
        }
    }
    __syncthreads();
    // pre-issue expects for steps 0 and 1 (before any peer store can land)
    if (tid == 0) { expect_tx(bar_a, 2048); expect_tx(bar_a + 8, 2048); }
    asm volatile("barrier.cluster.arrive.aligned;" ::: "memory");
    asm volatile("barrier.cluster.wait.aligned;" ::: "memory");

    const float INV0 = 1.0f / (QM * QL0 * 1536.0f);
    const float INV1 = 1.0f / (QM * QL1 * 1536.0f);

    for (int s = 0; s < TT - 1; ++s) {
        const int p = s & 1;
        const unsigned parity = (unsigned)((s >> 1) & 1);
        const int skill = skl_s[s];

        if (tid < 512) {
            // phase 1
            unsigned long long aB = 0ull, aN = 0ull;
            const float2* u2 = (const float2*)(ubuf + p * 32);
            const float2* f2 = (const float2*)(ufbuf + p * 32);
#pragma unroll
            for (int i = 0; i < 16; i++) {
                float2 uu2 = u2[i], ff2 = f2[i];
                fma_x2(aB, packf2(uu2.x, uu2.y), nr2[i]);
                fma_x2(aN, packf2(ff2.x, ff2.y), ns2[i]);
            }
            float2 rb = unpackf2(aB), rn = unpackf2(aN);
            const float bt = rb.x + rb.y + __expf(-del_s[s] * 0.1f * nlf_reg) * lp_reg;
            nlf_reg = rn.x + rn.y;

            // DP4A GEMV
            int acc = 0;
            const int4* mp4 = (const int4*)(mq + tid * MROW);
            const int4* lp4 = (const int4*)(lpq + p * 256);
#pragma unroll
            for (int i = 0; i < 16; i++) {
                int4 mv = mp4[i];
                int4 lv = lp4[i];
                acc = __dp4a(mv.x, lv.x, acc);
                acc = __dp4a(mv.y, lv.y, acc);
                acc = __dp4a(mv.z, lv.z, acc);
                acc = __dp4a(mv.w, lv.w, acc);
            }
            const float pl = (float)acc;

            // vectorized exchange: gather 4 partials per quad, 128 st.async.v4
            const unsigned fullm = 0xffffffffu;
            const float p1 = __shfl_down_sync(fullm, pl, 1);
            const float p2 = __shfl_down_sync(fullm, pl, 2);
            const float p3 = __shfl_down_sync(fullm, pl, 3);
            if ((tid & 3) == 0)
                st_async_v4(r_pr + (unsigned)(p * 512 + tid) * 4,
                            make_float4(pl, p1, p2, p3),
                            r_bar + (unsigned)p * 8);

            // wait peer half
            bar_wait_acq(bar_a + (unsigned)p * 8, parity);
            if (tid == 0 && s + 2 < TT - 1) expect_tx(bar_a + (unsigned)p * 8, 2048);

            const float INVs = (s == 0) ? INV0 : INV1;
            const float x = bt + (pl + partR[p * 512 + tid]) * INVs;
            const float cur = 1.0f / (1.0f + __expf(-x));
            lp_reg = cur;
            if ((tid >> 8) == (int)rank) {
                int q = __float2int_rn(cur * QL1);
                lpq[(p ^ 1) * 256 + (tid - rank * 256)] = (char)q;
            }
            if (rank == 0 && tid == skill) out[s * BSZ + b] = cur;
        } else {
            // MLP warps
            const int m = tid - 512;
            const int o = m & 31;
            const float lab = lab_s[s];
            if (m < 64) skc[m] = __ldg(nemb + skill * 64 + m);
            BAR1();
            {
                const int q = m >> 5;
                float hp = 0.f;
#pragma unroll
                for (int cc = 0; cc < 8; cc++) {
                    const int c = q * 8 + cc;
                    const float u0 = ubuf[p * 32 + c], u1 = ufbuf[p * 32 + c];
                    const float u3 = skc[32 + c], u4 = skc[c];
                    const float* wv = w1t + c * 160 + o;
                    hp += u0 * wv[0] + u1 * wv[32] + lab * wv[64] + u3 * wv[96] + u4 * wv[128];
                }
                mlpp[q * 32 + o] = hp;
            }
            BAR1();
            if (m < 32) hbuf[o] = fmaxf(bias[o] + mlpp[o] + mlpp[32 + o] + mlpp[64 + o] + mlpp[96 + o], 0.f);
            BAR1();
            {
                const int q = m >> 5;
                float up = 0.f;
#pragma unroll
                for (int ii = 0; ii < 8; ii++) {
                    const int i2 = q * 8 + ii;
                    up += hbuf[i2] * w2t[i2 * 32 + o];
                }
                mlpp[q * 32 + o] = up;
            }
            BAR1();
            if (m < 32) uubuf[o] = bias[32 + o] + mlpp[o] + mlpp[32 + o] + mlpp[64 + o] + mlpp[96 + o];
            BAR1();
            {
                float ap = 0.f;
                if (m < 64) {
                    const int q2 = m >> 5;
#pragma unroll
                    for (int ii = 0; ii < 16; ii++) {
                        const int i2 = q2 * 16 + ii;
                        ap += uubuf[i2] * wft[i2 * 32 + o];
                    }
                    mlpp[q2 * 32 + o] = ap;
                } else {
                    const int q2 = (m - 64) >> 5;
#pragma unroll
                    for (int ii = 0; ii < 16; ii++) {
                        const int i2 = q2 * 16 + ii;
                        ap += uubuf[i2] * wbt[i2 * 32 + o];
                    }
                    mlpp[64 + q2 * 32 + o] = ap;
                }
            }
            BAR1();
            if (m < 32) {
                ufbuf[(p ^ 1) * 32 + o] = tanhf(bias[64 + o] + mlpp[o] + mlpp[32 + o]);
                ubuf[(p ^ 1) * 32 + o]  = tanhf(bias[96 + o] + mlpp[64 + o] + mlpp[96 + o]);
            }
        }
        __syncthreads();
    }
    asm volatile("barrier.cluster.arrive.aligned;" ::: "memory");
    asm volatile("barrier.cluster.wait.aligned;" ::: "memory");
}

// ---------------------------------------------------------------------------
extern "C" void kernel_launch(void* const* d_in, const int* in_sizes, int n_in,
                              void* d_out, int out_size) {
    const int*   skills = (const int*)  d_in[0];
    const int*   times_ = (const int*)  d_in[1];
    const float* labels = (const float*)d_in[2];
    const float* adj    = (const float*)d_in[3];
    const float* nemb   = (const float*)d_in[4];
    const float* ub0    = (const float*)d_in[5];
    const float* uf0    = (const float*)d_in[6];
    const float* cw1    = (const float*)d_in[7];
    const float* cb1    = (const float*)d_in[8];
    const float* cw2    = (const float*)d_in[9];
    const float* cb2    = (const float*)d_in[10];
    const float* lfw    = (const float*)d_in[11];
    const float* lfb    = (const float*)d_in[12];
    const float* lbw    = (const float*)d_in[13];
    const float* lbb    = (const float*)d_in[14];

    void *pP = nullptr, *pQ = nullptr, *pM = nullptr;
    cudaGetSymbolAddress(&pP, g_P);
    cudaGetSymbolAddress(&pQ, g_Q);
    cudaGetSymbolAddress(&pM, g_M);
    __nv_bfloat16* P = (__nv_bfloat16*)pP;
    __nv_bfloat16* Q = (__nv_bfloat16*)pQ;
    __nv_bfloat16* M = (__nv_bfloat16*)pM;

    cudaFuncSetAttribute(k_gemm, cudaFuncAttributeMaxDynamicSharedMemorySize, GEMM_SMEM);
    cudaFuncSetAttribute(k_scan, cudaFuncAttributeMaxDynamicSharedMemorySize, SCAN_SMEM);

    k_convert<<<16384, 256>>>(adj, P);
    dim3 g(4, 4, 64);
    k_gemm<<<g, 256, GEMM_SMEM>>>(P, P, Q, nullptr, nullptr);
    k_gemm<<<g, 256, GEMM_SMEM>>>(Q, P, M, P, Q);     // M = Q@P + P + Q
    k_scan<<<2 * BSZ, 640, SCAN_SMEM>>>(skills, times_, labels, nemb, ub0, uf0,
                                        cw1, cb1, cw2, cb2, lfw, lfb, lbw, lbb,
                                        M, (float*)d_out);
}